// round 1
// baseline (speedup 1.0000x reference)
#include <cuda_runtime.h>
#include <math.h>
#include <stdint.h>

// Problem dims (fixed by the dataset)
#define NN 100000
#define CC 256
#define HH 128
#define KK 64
#define EE 1600000
#define ELN (EE + NN)          // edges + self loops = 1,700,000
#define NB ((NN + 1023) / 1024) // scan blocks = 98

// ---------------------------------------------------------------------------
// Device scratch (static: no allocation allowed)
// ---------------------------------------------------------------------------
__device__ float g_h1[(size_t)NN * HH];   // embed @ W1
__device__ float g_x1[(size_t)NN * HH];   // relu(agg1 + b1)
__device__ float g_h2[(size_t)NN * KK];   // x1 @ W2
__device__ float g_s[NN];                 // h . a_src
__device__ float g_d[NN];                 // h . a_dst
__device__ float g_elog[ELN];             // per-edge leakyrelu logits
__device__ int   g_deg[NN];
__device__ int   g_rowstart[NN + 1];
__device__ int   g_cursor[NN];
__device__ int   g_csrc[ELN];             // CSR (by dst): source node ids
__device__ int   g_bsum[NB];
__device__ int   g_boff[NB];

// ---------------------------------------------------------------------------
// CSR build: histogram -> scan -> fill
// ---------------------------------------------------------------------------
__global__ void k_zero() {
    int i = blockIdx.x * blockDim.x + threadIdx.x;
    if (i < NN) { g_deg[i] = 0; g_cursor[i] = 0; }
}

__global__ void k_hist(const int* __restrict__ ei) {
    int idx = blockIdx.x * blockDim.x + threadIdx.x;
    if (idx >= ELN) return;
    int dst = (idx < EE) ? ei[EE + idx] : (idx - EE);
    atomicAdd(&g_deg[dst], 1);
}

__global__ void k_scan1() {  // 1024 threads/block, block sum of deg chunk
    __shared__ int sm[1024];
    int t = threadIdx.x;
    int i = blockIdx.x * 1024 + t;
    sm[t] = (i < NN) ? g_deg[i] : 0;
    __syncthreads();
    for (int o = 512; o > 0; o >>= 1) {
        if (t < o) sm[t] += sm[t + o];
        __syncthreads();
    }
    if (t == 0) g_bsum[blockIdx.x] = sm[0];
}

__global__ void k_scan2() {  // single thread: scan 98 partials
    int run = 0;
    for (int b = 0; b < NB; b++) { g_boff[b] = run; run += g_bsum[b]; }
    g_rowstart[NN] = ELN;
}

__global__ void k_scan3() {  // Hillis-Steele exclusive scan within chunk
    __shared__ int buf[2][1024];
    int t = threadIdx.x;
    int i = blockIdx.x * 1024 + t;
    int v = (i < NN) ? g_deg[i] : 0;
    buf[0][t] = v;
    __syncthreads();
    int cur = 0;
    for (int o = 1; o < 1024; o <<= 1) {
        int nv = buf[cur][t] + ((t >= o) ? buf[cur][t - o] : 0);
        buf[cur ^ 1][t] = nv;
        cur ^= 1;
        __syncthreads();
    }
    if (i < NN) g_rowstart[i] = g_boff[blockIdx.x] + buf[cur][t] - v;
}

__global__ void k_fill(const int* __restrict__ ei) {
    int idx = blockIdx.x * blockDim.x + threadIdx.x;
    if (idx >= ELN) return;
    int src, dst;
    if (idx < EE) { src = ei[idx]; dst = ei[EE + idx]; }
    else          { src = dst = idx - EE; }
    int pos = atomicAdd(&g_cursor[dst], 1);
    g_csrc[g_rowstart[dst] + pos] = src;
}

// ---------------------------------------------------------------------------
// fp32 register-tiled GEMM: C[N x NOUT] = A[N x KIN] @ B[KIN x NOUT]
// 64x64 block tile, BK=16, 256 threads, 4x4 per thread.
// ---------------------------------------------------------------------------
template <int KIN, int NOUT, bool USE_X1>
__global__ void __launch_bounds__(256) k_gemm(const float* __restrict__ Aext,
                                              const float* __restrict__ B) {
    const float* A = USE_X1 ? g_x1 : Aext;
    float*       C = USE_X1 ? g_h2 : g_h1;

    __shared__ float As[16][64];
    __shared__ float Bs[16][64];

    int tid = threadIdx.x;
    int tx = tid & 15, ty = tid >> 4;
    int rowBase = blockIdx.y * 64;
    int colBase = blockIdx.x * 64;

    // load mapping
    int lr = tid >> 2;          // 0..63 (A row within tile)
    int lk = (tid & 3) * 4;     // 0,4,8,12 (A k offset)
    int bk = tid >> 4;          // 0..15 (B k row)
    int bn = (tid & 15) * 4;    // B col offset

    float acc[4][4] = {};

    for (int kt = 0; kt < KIN; kt += 16) {
        float4 a4 = make_float4(0.f, 0.f, 0.f, 0.f);
        if (rowBase + lr < NN)
            a4 = *(const float4*)&A[(size_t)(rowBase + lr) * KIN + kt + lk];
        As[lk + 0][lr] = a4.x;
        As[lk + 1][lr] = a4.y;
        As[lk + 2][lr] = a4.z;
        As[lk + 3][lr] = a4.w;
        *(float4*)&Bs[bk][bn] =
            *(const float4*)&B[(size_t)(kt + bk) * NOUT + colBase + bn];
        __syncthreads();

#pragma unroll
        for (int kk = 0; kk < 16; kk++) {
            float4 av = *(float4*)&As[kk][ty * 4];
            float4 bv = *(float4*)&Bs[kk][tx * 4];
            acc[0][0] += av.x * bv.x; acc[0][1] += av.x * bv.y;
            acc[0][2] += av.x * bv.z; acc[0][3] += av.x * bv.w;
            acc[1][0] += av.y * bv.x; acc[1][1] += av.y * bv.y;
            acc[1][2] += av.y * bv.z; acc[1][3] += av.y * bv.w;
            acc[2][0] += av.z * bv.x; acc[2][1] += av.z * bv.y;
            acc[2][2] += av.z * bv.z; acc[2][3] += av.z * bv.w;
            acc[3][0] += av.w * bv.x; acc[3][1] += av.w * bv.y;
            acc[3][2] += av.w * bv.z; acc[3][3] += av.w * bv.w;
        }
        __syncthreads();
    }

#pragma unroll
    for (int i = 0; i < 4; i++) {
        int r = rowBase + ty * 4 + i;
        if (r < NN)
            *(float4*)&C[(size_t)r * NOUT + colBase + tx * 4] =
                make_float4(acc[i][0], acc[i][1], acc[i][2], acc[i][3]);
    }
}

// ---------------------------------------------------------------------------
// s/d projections: warp per node
// ---------------------------------------------------------------------------
template <int F, bool USE_H2>
__global__ void k_sd(const float* __restrict__ asrc,
                     const float* __restrict__ adst) {
    int w = (blockIdx.x * blockDim.x + threadIdx.x) >> 5;
    int lane = threadIdx.x & 31;
    if (w >= NN) return;
    const float* h = (USE_H2 ? g_h2 : g_h1) + (size_t)w * F;
    float s = 0.f, d = 0.f;
#pragma unroll
    for (int k = lane; k < F; k += 32) {
        float hv = h[k];
        s += hv * __ldg(&asrc[k]);
        d += hv * __ldg(&adst[k]);
    }
#pragma unroll
    for (int o = 16; o; o >>= 1) {
        s += __shfl_xor_sync(0xffffffffu, s, o);
        d += __shfl_xor_sync(0xffffffffu, d, o);
    }
    if (lane == 0) { g_s[w] = s; g_d[w] = d; }
}

// ---------------------------------------------------------------------------
// Pull-mode attention aggregation: warp per dst node.
// ACT==0: out = relu(agg + bias) -> g_x1 (layer 1, F=128)
// ACT==1: out = sigmoid(agg + bias) -> d_out (layer 2, F=64)
// ---------------------------------------------------------------------------
template <int F, int ACT>
__global__ void k_agg(const float* __restrict__ bias,
                      float* __restrict__ outp) {
    constexpr int V = F / 32;
    int w = (blockIdx.x * blockDim.x + threadIdx.x) >> 5;
    int lane = threadIdx.x & 31;
    if (w >= NN) return;

    int rs = g_rowstart[w];
    int re = g_rowstart[w + 1];
    float dn = g_d[w];

    // pass 1: logits + max
    float m = -1e30f;
    for (int j = rs + lane; j < re; j += 32) {
        float l = g_s[g_csrc[j]] + dn;
        l = (l > 0.f) ? l : 0.2f * l;   // leaky_relu(0.2)
        g_elog[j] = l;
        m = fmaxf(m, l);
    }
#pragma unroll
    for (int o = 16; o; o >>= 1) m = fmaxf(m, __shfl_xor_sync(0xffffffffu, m, o));

    // pass 2: sum of exp
    float sum = 0.f;
    for (int j = rs + lane; j < re; j += 32) sum += __expf(g_elog[j] - m);
#pragma unroll
    for (int o = 16; o; o >>= 1) sum += __shfl_xor_sync(0xffffffffu, sum, o);
    float inv = 1.f / (sum + 1e-16f);
    __syncwarp();

    // pass 3: weighted gather of h[src]
    float acc[V];
#pragma unroll
    for (int t = 0; t < V; t++) acc[t] = 0.f;

    const float* h = (ACT == 0) ? g_h1 : g_h2;
    for (int j = rs; j < re; j++) {
        int s = g_csrc[j];                       // broadcast load
        float a = __expf(g_elog[j] - m) * inv;   // broadcast load
        if (V == 4) {
            float4 v = *(const float4*)&h[(size_t)s * F + lane * 4];
            acc[0] += a * v.x; acc[1] += a * v.y;
            acc[2] += a * v.z; acc[3] += a * v.w;
        } else {
            float2 v = *(const float2*)&h[(size_t)s * F + lane * 2];
            acc[0] += a * v.x; acc[1] += a * v.y;
        }
    }

#pragma unroll
    for (int t = 0; t < V; t++) {
        float o = acc[t] + __ldg(&bias[lane * V + t]);
        if (ACT == 0) {
            g_x1[(size_t)w * F + lane * V + t] = fmaxf(o, 0.f);
        } else {
            outp[(size_t)w * F + lane * V + t] = 1.f / (1.f + __expf(-o));
        }
    }
}

// ---------------------------------------------------------------------------
// Launch
// ---------------------------------------------------------------------------
extern "C" void kernel_launch(void* const* d_in, const int* in_sizes, int n_in,
                              void* d_out, int out_size) {
    const int*   ei    = (const int*)d_in[0];
    const float* embed = (const float*)d_in[1];
    const float* W1    = (const float*)d_in[2];
    const float* as1   = (const float*)d_in[3];
    const float* ad1   = (const float*)d_in[4];
    const float* b1    = (const float*)d_in[5];
    const float* W2    = (const float*)d_in[6];
    const float* as2   = (const float*)d_in[7];
    const float* ad2   = (const float*)d_in[8];
    const float* b2    = (const float*)d_in[9];
    float* out = (float*)d_out;

    // CSR build
    k_zero<<<(NN + 255) / 256, 256>>>();
    k_hist<<<(ELN + 255) / 256, 256>>>(ei);
    k_scan1<<<NB, 1024>>>();
    k_scan2<<<1, 1>>>();
    k_scan3<<<NB, 1024>>>();
    k_fill<<<(ELN + 255) / 256, 256>>>(ei);

    int warpBlocks = (NN * 32 + 255) / 256;  // warp-per-node kernels

    // Layer 1
    k_gemm<CC, HH, false><<<dim3(HH / 64, (NN + 63) / 64), 256>>>(embed, W1);
    k_sd<HH, false><<<warpBlocks, 256>>>(as1, ad1);
    k_agg<HH, 0><<<warpBlocks, 256>>>(b1, nullptr);

    // Layer 2
    k_gemm<HH, KK, true><<<dim3(KK / 64, (NN + 63) / 64), 256>>>(nullptr, W2);
    k_sd<KK, true><<<warpBlocks, 256>>>(as2, ad2);
    k_agg<KK, 1><<<warpBlocks, 256>>>(b2, out);
}

// round 2
// speedup vs baseline: 1.4048x; 1.4048x over previous
#include <cuda_runtime.h>
#include <math.h>
#include <stdint.h>

// Problem dims (fixed by the dataset)
#define NN 100000
#define CC 256
#define HH 128
#define KK 64
#define EE 1600000
#define ELN (EE + NN)          // edges + self loops = 1,700,000
#define NB ((NN + 1023) / 1024) // scan blocks = 98

// ---------------------------------------------------------------------------
// Device scratch (static: no allocation allowed)
// ---------------------------------------------------------------------------
__device__ float g_h1[(size_t)NN * HH];   // embed @ W1
__device__ float g_x1[(size_t)NN * HH];   // relu(agg1 + b1)
__device__ float g_h2[(size_t)NN * KK];   // x1 @ W2
__device__ float g_s[NN];                 // h . a_src
__device__ float g_d[NN];                 // h . a_dst
__device__ float g_elog[ELN];             // per-edge leakyrelu logits
__device__ int   g_deg[NN];
__device__ int   g_rowstart[NN + 1];
__device__ int   g_cursor[NN];
__device__ int   g_csrc[ELN];             // CSR (by dst): source node ids
__device__ int   g_bsum[NB];
__device__ int   g_boff[NB];

// ---------------------------------------------------------------------------
// CSR build: histogram -> scan -> fill
// ---------------------------------------------------------------------------
__global__ void k_zero() {
    int i = blockIdx.x * blockDim.x + threadIdx.x;
    if (i < NN) { g_deg[i] = 0; g_cursor[i] = 0; }
}

__global__ void k_hist(const int* __restrict__ ei) {
    int idx = blockIdx.x * blockDim.x + threadIdx.x;
    if (idx >= ELN) return;
    int dst = (idx < EE) ? ei[EE + idx] : (idx - EE);
    atomicAdd(&g_deg[dst], 1);
}

__global__ void k_scan1() {  // 1024 threads/block, block sum of deg chunk
    __shared__ int sm[1024];
    int t = threadIdx.x;
    int i = blockIdx.x * 1024 + t;
    sm[t] = (i < NN) ? g_deg[i] : 0;
    __syncthreads();
    for (int o = 512; o > 0; o >>= 1) {
        if (t < o) sm[t] += sm[t + o];
        __syncthreads();
    }
    if (t == 0) g_bsum[blockIdx.x] = sm[0];
}

__global__ void k_scan2() {  // one warp scans NB partials
    int lane = threadIdx.x;
    int run = 0;
    for (int base = 0; base < NB; base += 32) {
        int orig = (base + lane < NB) ? g_bsum[base + lane] : 0;
        int v = orig;
#pragma unroll
        for (int o = 1; o < 32; o <<= 1) {
            int t = __shfl_up_sync(0xffffffffu, v, o);
            if (lane >= o) v += t;
        }
        if (base + lane < NB) g_boff[base + lane] = run + v - orig;
        run += __shfl_sync(0xffffffffu, v, 31);
    }
    if (lane == 0) g_rowstart[NN] = ELN;
}

__global__ void k_scan3() {  // Hillis-Steele exclusive scan within chunk
    __shared__ int buf[2][1024];
    int t = threadIdx.x;
    int i = blockIdx.x * 1024 + t;
    int v = (i < NN) ? g_deg[i] : 0;
    buf[0][t] = v;
    __syncthreads();
    int cur = 0;
    for (int o = 1; o < 1024; o <<= 1) {
        int nv = buf[cur][t] + ((t >= o) ? buf[cur][t - o] : 0);
        buf[cur ^ 1][t] = nv;
        cur ^= 1;
        __syncthreads();
    }
    if (i < NN) g_rowstart[i] = g_boff[blockIdx.x] + buf[cur][t] - v;
}

__global__ void k_fill(const int* __restrict__ ei) {
    int idx = blockIdx.x * blockDim.x + threadIdx.x;
    if (idx >= ELN) return;
    int src, dst;
    if (idx < EE) { src = ei[idx]; dst = ei[EE + idx]; }
    else          { src = dst = idx - EE; }
    int pos = atomicAdd(&g_cursor[dst], 1);
    g_csrc[g_rowstart[dst] + pos] = src;
}

// ---------------------------------------------------------------------------
// tf32 tensor-core GEMM: C[M x NOUT] = A[M x KIN] @ B[KIN x NOUT]
// BM=128, BN=NOUT (128 or 64), BK=32. 256 threads = 8 warps (4x2).
// Warp tile: 32 x BN/2 via m16n8k8 tf32 mma.
// ---------------------------------------------------------------------------
__device__ __forceinline__ uint32_t f2tf32(float x) {
    uint32_t r;
    asm("cvt.rna.tf32.f32 %0, %1;" : "=r"(r) : "f"(x));
    return r;
}

__device__ __forceinline__ void mma_tf32(float* c, const uint32_t* a,
                                         const uint32_t* b) {
    asm volatile(
        "mma.sync.aligned.m16n8k8.row.col.f32.tf32.tf32.f32 "
        "{%0,%1,%2,%3}, {%4,%5,%6,%7}, {%8,%9}, {%0,%1,%2,%3};\n"
        : "+f"(c[0]), "+f"(c[1]), "+f"(c[2]), "+f"(c[3])
        : "r"(a[0]), "r"(a[1]), "r"(a[2]), "r"(a[3]), "r"(b[0]), "r"(b[1]));
}

template <int KIN, int NOUT, bool USE_X1>
__global__ void __launch_bounds__(256) k_gemm_tc(const float* __restrict__ Aext,
                                                 const float* __restrict__ B) {
    const float* A = USE_X1 ? g_x1 : Aext;
    float*       C = USE_X1 ? g_h2 : g_h1;

    constexpr int BN = NOUT;            // whole output width per block
    constexpr int NT = BN / 16;         // n-subtiles per warp (8 or 4)
    constexpr int BKP = 132;            // padded As row (keeps 16B align)
    constexpr int BNP = BN + 4;

    __shared__ uint32_t As[32][BKP];    // [k][m]
    __shared__ uint32_t Bs[32][BNP];    // [k][n]

    int tid = threadIdx.x;
    int lane = tid & 31, wid = tid >> 5;
    int warpM = (wid >> 1) * 32;
    int warpN = (wid & 1) * (BN / 2);
    int qr = lane >> 2;   // 0..7
    int qc = lane & 3;    // 0..3
    int rowBase = blockIdx.x * 128;

    float acc[2][NT][4];
#pragma unroll
    for (int mt = 0; mt < 2; mt++)
#pragma unroll
        for (int nt = 0; nt < NT; nt++)
#pragma unroll
            for (int i = 0; i < 4; i++) acc[mt][nt][i] = 0.f;

    for (int kt = 0; kt < KIN; kt += 32) {
        // load A tile (128x32), transpose into As[k][m], convert to tf32
#pragma unroll
        for (int i = 0; i < 4; i++) {
            int idx = tid + i * 256;         // float4 index, 8 per row
            int r = idx >> 3;
            int k4 = (idx & 7) * 4;
            float4 v = make_float4(0.f, 0.f, 0.f, 0.f);
            if (rowBase + r < NN)
                v = *(const float4*)&A[(size_t)(rowBase + r) * KIN + kt + k4];
            As[k4 + 0][r] = f2tf32(v.x);
            As[k4 + 1][r] = f2tf32(v.y);
            As[k4 + 2][r] = f2tf32(v.z);
            As[k4 + 3][r] = f2tf32(v.w);
        }
        // load B tile (32 x BN) into Bs[k][n]
#pragma unroll
        for (int i = 0; i < (32 * BN / 4) / 256; i++) {
            int idx = tid + i * 256;         // float4 index
            int k = idx / (BN / 4);
            int n4 = (idx % (BN / 4)) * 4;
            float4 v = *(const float4*)&B[(size_t)(kt + k) * NOUT + n4];
            Bs[k][n4 + 0] = f2tf32(v.x);
            Bs[k][n4 + 1] = f2tf32(v.y);
            Bs[k][n4 + 2] = f2tf32(v.z);
            Bs[k][n4 + 3] = f2tf32(v.w);
        }
        __syncthreads();

#pragma unroll
        for (int ks = 0; ks < 4; ks++) {
            int k0 = ks * 8;
            uint32_t afr[2][4];
#pragma unroll
            for (int mt = 0; mt < 2; mt++) {
                int m0 = warpM + mt * 16 + qr;
                afr[mt][0] = As[k0 + qc][m0];
                afr[mt][1] = As[k0 + qc][m0 + 8];
                afr[mt][2] = As[k0 + 4 + qc][m0];
                afr[mt][3] = As[k0 + 4 + qc][m0 + 8];
            }
            uint32_t bfr[NT][2];
#pragma unroll
            for (int nt = 0; nt < NT; nt++) {
                int n0 = warpN + nt * 8 + qr;
                bfr[nt][0] = Bs[k0 + qc][n0];
                bfr[nt][1] = Bs[k0 + 4 + qc][n0];
            }
#pragma unroll
            for (int mt = 0; mt < 2; mt++)
#pragma unroll
                for (int nt = 0; nt < NT; nt++)
                    mma_tf32(acc[mt][nt], afr[mt], bfr[nt]);
        }
        __syncthreads();
    }

    // epilogue
#pragma unroll
    for (int mt = 0; mt < 2; mt++) {
        int r0 = rowBase + warpM + mt * 16 + qr;
        int r1 = r0 + 8;
#pragma unroll
        for (int nt = 0; nt < NT; nt++) {
            int col = warpN + nt * 8 + qc * 2;
            if (r0 < NN)
                *(float2*)&C[(size_t)r0 * NOUT + col] =
                    make_float2(acc[mt][nt][0], acc[mt][nt][1]);
            if (r1 < NN)
                *(float2*)&C[(size_t)r1 * NOUT + col] =
                    make_float2(acc[mt][nt][2], acc[mt][nt][3]);
        }
    }
}

// ---------------------------------------------------------------------------
// s/d projections: warp per node
// ---------------------------------------------------------------------------
template <int F, bool USE_H2>
__global__ void k_sd(const float* __restrict__ asrc,
                     const float* __restrict__ adst) {
    int w = (blockIdx.x * blockDim.x + threadIdx.x) >> 5;
    int lane = threadIdx.x & 31;
    if (w >= NN) return;
    const float* h = (USE_H2 ? g_h2 : g_h1) + (size_t)w * F;
    float s = 0.f, d = 0.f;
#pragma unroll
    for (int k = lane; k < F; k += 32) {
        float hv = h[k];
        s += hv * __ldg(&asrc[k]);
        d += hv * __ldg(&adst[k]);
    }
#pragma unroll
    for (int o = 16; o; o >>= 1) {
        s += __shfl_xor_sync(0xffffffffu, s, o);
        d += __shfl_xor_sync(0xffffffffu, d, o);
    }
    if (lane == 0) { g_s[w] = s; g_d[w] = d; }
}

// ---------------------------------------------------------------------------
// Pull-mode attention aggregation: warp per dst node.
// ACT==0: out = relu(agg + bias) -> g_x1 (layer 1, F=128)
// ACT==1: out = sigmoid(agg + bias) -> d_out (layer 2, F=64)
// ---------------------------------------------------------------------------
template <int F, int ACT>
__global__ void k_agg(const float* __restrict__ bias,
                      float* __restrict__ outp) {
    constexpr int V = F / 32;
    int w = (blockIdx.x * blockDim.x + threadIdx.x) >> 5;
    int lane = threadIdx.x & 31;
    if (w >= NN) return;

    int rs = g_rowstart[w];
    int re = g_rowstart[w + 1];
    float dn = g_d[w];

    // pass 1: logits + max
    float m = -1e30f;
    for (int j = rs + lane; j < re; j += 32) {
        float l = g_s[g_csrc[j]] + dn;
        l = (l > 0.f) ? l : 0.2f * l;   // leaky_relu(0.2)
        g_elog[j] = l;
        m = fmaxf(m, l);
    }
#pragma unroll
    for (int o = 16; o; o >>= 1) m = fmaxf(m, __shfl_xor_sync(0xffffffffu, m, o));

    // pass 2: sum of exp
    float sum = 0.f;
    for (int j = rs + lane; j < re; j += 32) sum += __expf(g_elog[j] - m);
#pragma unroll
    for (int o = 16; o; o >>= 1) sum += __shfl_xor_sync(0xffffffffu, sum, o);
    float inv = 1.f / (sum + 1e-16f);
    __syncwarp();

    // pass 3: weighted gather of h[src]
    float acc[V];
#pragma unroll
    for (int t = 0; t < V; t++) acc[t] = 0.f;

    const float* h = (ACT == 0) ? g_h1 : g_h2;
    for (int j = rs; j < re; j++) {
        int s = g_csrc[j];                       // broadcast load
        float a = __expf(g_elog[j] - m) * inv;   // broadcast load
        if (V == 4) {
            float4 v = *(const float4*)&h[(size_t)s * F + lane * 4];
            acc[0] += a * v.x; acc[1] += a * v.y;
            acc[2] += a * v.z; acc[3] += a * v.w;
        } else {
            float2 v = *(const float2*)&h[(size_t)s * F + lane * 2];
            acc[0] += a * v.x; acc[1] += a * v.y;
        }
    }

#pragma unroll
    for (int t = 0; t < V; t++) {
        float o = acc[t] + __ldg(&bias[lane * V + t]);
        if (ACT == 0) {
            g_x1[(size_t)w * F + lane * V + t] = fmaxf(o, 0.f);
        } else {
            outp[(size_t)w * F + lane * V + t] = 1.f / (1.f + __expf(-o));
        }
    }
}

// ---------------------------------------------------------------------------
// Launch
// ---------------------------------------------------------------------------
extern "C" void kernel_launch(void* const* d_in, const int* in_sizes, int n_in,
                              void* d_out, int out_size) {
    const int*   ei    = (const int*)d_in[0];
    const float* embed = (const float*)d_in[1];
    const float* W1    = (const float*)d_in[2];
    const float* as1   = (const float*)d_in[3];
    const float* ad1   = (const float*)d_in[4];
    const float* b1    = (const float*)d_in[5];
    const float* W2    = (const float*)d_in[6];
    const float* as2   = (const float*)d_in[7];
    const float* ad2   = (const float*)d_in[8];
    const float* b2    = (const float*)d_in[9];
    float* out = (float*)d_out;

    // CSR build
    k_zero<<<(NN + 255) / 256, 256>>>();
    k_hist<<<(ELN + 255) / 256, 256>>>(ei);
    k_scan1<<<NB, 1024>>>();
    k_scan2<<<1, 32>>>();
    k_scan3<<<NB, 1024>>>();
    k_fill<<<(ELN + 255) / 256, 256>>>(ei);

    int warpBlocks = (NN * 32 + 255) / 256;  // warp-per-node kernels
    int gemmBlocks = (NN + 127) / 128;

    // Layer 1
    k_gemm_tc<CC, HH, false><<<gemmBlocks, 256>>>(embed, W1);
    k_sd<HH, false><<<warpBlocks, 256>>>(as1, ad1);
    k_agg<HH, 0><<<warpBlocks, 256>>>(b1, nullptr);

    // Layer 2
    k_gemm_tc<HH, KK, true><<<gemmBlocks, 256>>>(nullptr, W2);
    k_sd<KK, true><<<warpBlocks, 256>>>(as2, ad2);
    k_agg<KK, 1><<<warpBlocks, 256>>>(b2, out);
}

// round 4
// speedup vs baseline: 1.6286x; 1.1593x over previous
#include <cuda_runtime.h>
#include <math.h>
#include <stdint.h>

// Problem dims (fixed by the dataset)
#define NN 100000
#define CC 256
#define HH 128
#define KK 64
#define EE 1600000
#define ELN (EE + NN)          // edges + self loops = 1,700,000
#define NB ((NN + 1023) / 1024) // scan blocks = 98

// ---------------------------------------------------------------------------
// Device scratch (static: no allocation allowed)
// ---------------------------------------------------------------------------
__device__ float g_h1[(size_t)NN * HH];   // embed @ W1
__device__ float g_x1[(size_t)NN * HH];   // relu(agg1 + b1)
__device__ float g_h2[(size_t)NN * KK];   // x1 @ W2
__device__ float g_s1[NN];                // h1 . a_src1
__device__ float g_d1[NN];                // h1 . a_dst1
__device__ float g_s2[NN];                // h2 . a_src2
__device__ float g_d2[NN];                // h2 . a_dst2
__device__ float g_elog[ELN];             // per-edge leakyrelu logits
__device__ int   g_deg[NN];
__device__ int   g_rowstart[NN + 1];
__device__ int   g_cursor[NN];
__device__ int   g_csrc[ELN];             // CSR (by dst): source node ids
__device__ int   g_bsum[NB];
__device__ int   g_boff[NB];

// ---------------------------------------------------------------------------
// CSR build: zero -> histogram -> scan -> fill
// ---------------------------------------------------------------------------
__global__ void k_zero() {
    int i = blockIdx.x * blockDim.x + threadIdx.x;
    if (i < NN) {
        g_deg[i] = 0; g_cursor[i] = 0;
        g_s1[i] = 0.f; g_d1[i] = 0.f;
        g_s2[i] = 0.f; g_d2[i] = 0.f;
    }
}

__global__ void k_hist(const int* __restrict__ ei) {
    int idx = blockIdx.x * blockDim.x + threadIdx.x;
    if (idx >= ELN) return;
    int dst = (idx < EE) ? ei[EE + idx] : (idx - EE);
    atomicAdd(&g_deg[dst], 1);
}

__global__ void k_scan1() {  // 1024 threads/block, block sum of deg chunk
    __shared__ int sm[1024];
    int t = threadIdx.x;
    int i = blockIdx.x * 1024 + t;
    sm[t] = (i < NN) ? g_deg[i] : 0;
    __syncthreads();
    for (int o = 512; o > 0; o >>= 1) {
        if (t < o) sm[t] += sm[t + o];
        __syncthreads();
    }
    if (t == 0) g_bsum[blockIdx.x] = sm[0];
}

__global__ void k_scan2() {  // one warp scans NB partials
    int lane = threadIdx.x;
    int run = 0;
    for (int base = 0; base < NB; base += 32) {
        int orig = (base + lane < NB) ? g_bsum[base + lane] : 0;
        int v = orig;
#pragma unroll
        for (int o = 1; o < 32; o <<= 1) {
            int t = __shfl_up_sync(0xffffffffu, v, o);
            if (lane >= o) v += t;
        }
        if (base + lane < NB) g_boff[base + lane] = run + v - orig;
        run += __shfl_sync(0xffffffffu, v, 31);
    }
    if (lane == 0) g_rowstart[NN] = ELN;
}

__global__ void k_scan3() {  // Hillis-Steele exclusive scan within chunk
    __shared__ int buf[2][1024];
    int t = threadIdx.x;
    int i = blockIdx.x * 1024 + t;
    int v = (i < NN) ? g_deg[i] : 0;
    buf[0][t] = v;
    __syncthreads();
    int cur = 0;
    for (int o = 1; o < 1024; o <<= 1) {
        int nv = buf[cur][t] + ((t >= o) ? buf[cur][t - o] : 0);
        buf[cur ^ 1][t] = nv;
        cur ^= 1;
        __syncthreads();
    }
    if (i < NN) g_rowstart[i] = g_boff[blockIdx.x] + buf[cur][t] - v;
}

__global__ void k_fill(const int* __restrict__ ei) {
    int idx = blockIdx.x * blockDim.x + threadIdx.x;
    if (idx >= ELN) return;
    int src, dst;
    if (idx < EE) { src = ei[idx]; dst = ei[EE + idx]; }
    else          { src = dst = idx - EE; }
    int pos = atomicAdd(&g_cursor[dst], 1);
    g_csrc[g_rowstart[dst] + pos] = src;
}

// ---------------------------------------------------------------------------
// tf32 tensor-core GEMM + fused s/d epilogue.
// C[M x NOUT] = A[M x KIN] @ B[KIN x NOUT]
// BM=128, BN=NOUT, BK=32, 256 threads = 8 warps (4x2 grid of 32 x BN/2 tiles).
// Register-prefetch pipelining; conflict-free smem (A [m][k] pad 36, B [k][n] pad +8).
// Epilogue also accumulates s = C.a_src, d = C.a_dst per row via quad-reduce +
// atomicAdd (2 warps contribute per row).
// ---------------------------------------------------------------------------
__device__ __forceinline__ uint32_t f2tf32(float x) {
    uint32_t r;
    asm("cvt.rna.tf32.f32 %0, %1;" : "=r"(r) : "f"(x));
    return r;
}

__device__ __forceinline__ void mma_tf32(float* c, const uint32_t* a,
                                         const uint32_t* b) {
    asm volatile(
        "mma.sync.aligned.m16n8k8.row.col.f32.tf32.tf32.f32 "
        "{%0,%1,%2,%3}, {%4,%5,%6,%7}, {%8,%9}, {%0,%1,%2,%3};\n"
        : "+f"(c[0]), "+f"(c[1]), "+f"(c[2]), "+f"(c[3])
        : "r"(a[0]), "r"(a[1]), "r"(a[2]), "r"(a[3]), "r"(b[0]), "r"(b[1]));
}

template <int KIN, int NOUT, bool LAYER2>
__global__ void __launch_bounds__(256) k_gemm_tc(const float* __restrict__ Aext,
                                                 const float* __restrict__ B,
                                                 const float* __restrict__ asrc,
                                                 const float* __restrict__ adst) {
    const float* A = LAYER2 ? g_x1 : Aext;
    float*       C = LAYER2 ? g_h2 : g_h1;
    float*       sOut = LAYER2 ? g_s2 : g_s1;
    float*       dOut = LAYER2 ? g_d2 : g_d1;

    constexpr int BN = NOUT;
    constexpr int NT = BN / 16;            // n-subtiles per warp
    constexpr int KP = 36;                 // A smem row pad (bank = 4*qr+qc)
    constexpr int BNP = BN + 8;            // B smem row pad (bank = 8*qc+qr)
    constexpr int TTILES = KIN / 32;
    constexpr int AV = 4;                  // 128*32/4 float4 / 256 threads
    constexpr int BV = (32 * BN / 4) / 256;

    __shared__ uint32_t As[128][KP];
    __shared__ uint32_t Bs[32][BNP];

    int tid = threadIdx.x;
    int lane = tid & 31, wid = tid >> 5;
    int warpM = (wid >> 1) * 32;
    int warpN = (wid & 1) * (BN / 2);
    int qr = lane >> 2;   // 0..7
    int qc = lane & 3;    // 0..3
    int rowBase = blockIdx.x * 128;

    // per-thread load coords
    int ar = tid >> 3;             // A row 0..31 (plus i*32)
    int ak = (tid & 7) * 4;        // A k offset
    int bkRow = tid / (BN / 4);    // B k row base
    int bn4 = (tid % (BN / 4)) * 4;

    float acc[2][NT][4];
#pragma unroll
    for (int mt = 0; mt < 2; mt++)
#pragma unroll
        for (int nt = 0; nt < NT; nt++)
#pragma unroll
            for (int i = 0; i < 4; i++) acc[mt][nt][i] = 0.f;

    float4 aR[AV], bR[BV];

    // prefetch tile 0
#pragma unroll
    for (int i = 0; i < AV; i++) {
        int r = ar + i * 32;
        aR[i] = (rowBase + r < NN)
                    ? *(const float4*)&A[(size_t)(rowBase + r) * KIN + ak]
                    : make_float4(0.f, 0.f, 0.f, 0.f);
    }
#pragma unroll
    for (int i = 0; i < BV; i++) {
        int kk = bkRow + i * (256 / (BN / 4));
        bR[i] = *(const float4*)&B[(size_t)kk * NOUT + bn4];
    }

    for (int kt = 0; kt < TTILES; kt++) {
        // store staged regs -> smem (tf32 convert)
#pragma unroll
        for (int i = 0; i < AV; i++) {
            int r = ar + i * 32;
            *(uint4*)&As[r][ak] = make_uint4(f2tf32(aR[i].x), f2tf32(aR[i].y),
                                             f2tf32(aR[i].z), f2tf32(aR[i].w));
        }
#pragma unroll
        for (int i = 0; i < BV; i++) {
            int kk = bkRow + i * (256 / (BN / 4));
            *(uint4*)&Bs[kk][bn4] = make_uint4(f2tf32(bR[i].x), f2tf32(bR[i].y),
                                               f2tf32(bR[i].z), f2tf32(bR[i].w));
        }
        __syncthreads();

        // prefetch next tile while computing
        if (kt + 1 < TTILES) {
            int kbase = (kt + 1) * 32;
#pragma unroll
            for (int i = 0; i < AV; i++) {
                int r = ar + i * 32;
                aR[i] = (rowBase + r < NN)
                            ? *(const float4*)&A[(size_t)(rowBase + r) * KIN +
                                                 kbase + ak]
                            : make_float4(0.f, 0.f, 0.f, 0.f);
            }
#pragma unroll
            for (int i = 0; i < BV; i++) {
                int kk = bkRow + i * (256 / (BN / 4));
                bR[i] = *(const float4*)&B[(size_t)(kbase + kk) * NOUT + bn4];
            }
        }

#pragma unroll
        for (int ks = 0; ks < 4; ks++) {
            int k0 = ks * 8;
            uint32_t afr[2][4];
#pragma unroll
            for (int mt = 0; mt < 2; mt++) {
                int m0 = warpM + mt * 16 + qr;
                afr[mt][0] = As[m0][k0 + qc];
                afr[mt][1] = As[m0 + 8][k0 + qc];
                afr[mt][2] = As[m0][k0 + 4 + qc];
                afr[mt][3] = As[m0 + 8][k0 + 4 + qc];
            }
            uint32_t bfr[NT][2];
#pragma unroll
            for (int nt = 0; nt < NT; nt++) {
                int n0 = warpN + nt * 8 + qr;
                bfr[nt][0] = Bs[k0 + qc][n0];
                bfr[nt][1] = Bs[k0 + 4 + qc][n0];
            }
#pragma unroll
            for (int mt = 0; mt < 2; mt++)
#pragma unroll
                for (int nt = 0; nt < NT; nt++)
                    mma_tf32(acc[mt][nt], afr[mt], bfr[nt]);
        }
        __syncthreads();
    }

    // epilogue: write C + fused s/d row projections
#pragma unroll
    for (int mt = 0; mt < 2; mt++) {
        int r0 = rowBase + warpM + mt * 16 + qr;
        int r1 = r0 + 8;
        float s0 = 0.f, d0 = 0.f, s1 = 0.f, d1 = 0.f;
#pragma unroll
        for (int nt = 0; nt < NT; nt++) {
            int col = warpN + nt * 8 + qc * 2;
            float a0 = __ldg(&asrc[col]), a1 = __ldg(&asrc[col + 1]);
            float e0 = __ldg(&adst[col]), e1 = __ldg(&adst[col + 1]);
            s0 += acc[mt][nt][0] * a0 + acc[mt][nt][1] * a1;
            d0 += acc[mt][nt][0] * e0 + acc[mt][nt][1] * e1;
            s1 += acc[mt][nt][2] * a0 + acc[mt][nt][3] * a1;
            d1 += acc[mt][nt][2] * e0 + acc[mt][nt][3] * e1;
            if (r0 < NN)
                *(float2*)&C[(size_t)r0 * NOUT + col] =
                    make_float2(acc[mt][nt][0], acc[mt][nt][1]);
            if (r1 < NN)
                *(float2*)&C[(size_t)r1 * NOUT + col] =
                    make_float2(acc[mt][nt][2], acc[mt][nt][3]);
        }
        // reduce over the quad (lanes qr*4 .. qr*4+3)
#pragma unroll
        for (int o = 1; o < 4; o <<= 1) {
            s0 += __shfl_xor_sync(0xffffffffu, s0, o);
            d0 += __shfl_xor_sync(0xffffffffu, d0, o);
            s1 += __shfl_xor_sync(0xffffffffu, s1, o);
            d1 += __shfl_xor_sync(0xffffffffu, d1, o);
        }
        if (qc == 0) {
            if (r0 < NN) { atomicAdd(&sOut[r0], s0); atomicAdd(&dOut[r0], d0); }
            if (r1 < NN) { atomicAdd(&sOut[r1], s1); atomicAdd(&dOut[r1], d1); }
        }
    }
}

// ---------------------------------------------------------------------------
// Pull-mode attention aggregation: warp per dst node. Two passes:
//  pass 1: logits + warp max (lane-parallel over edges)
//  pass 2: fused Sum(e) and Sum(e*h) accumulation, normalize at the end
// ACT==0: out = relu(agg + bias) -> g_x1 (layer 1, F=128)
// ACT==1: out = sigmoid(agg + bias) -> d_out (layer 2, F=64)
// ---------------------------------------------------------------------------
template <int F, int ACT>
__global__ void k_agg(const float* __restrict__ bias,
                      float* __restrict__ outp) {
    constexpr int V = F / 32;
    int w = (blockIdx.x * blockDim.x + threadIdx.x) >> 5;
    int lane = threadIdx.x & 31;
    if (w >= NN) return;

    const float* gs = (ACT == 0) ? g_s1 : g_s2;
    float dn = ((ACT == 0) ? g_d1 : g_d2)[w];
    int rs = g_rowstart[w];
    int re = g_rowstart[w + 1];

    // pass 1: logits + max
    float m = -1e30f;
    for (int j = rs + lane; j < re; j += 32) {
        float l = gs[g_csrc[j]] + dn;
        l = (l > 0.f) ? l : 0.2f * l;   // leaky_relu(0.2)
        g_elog[j] = l;
        m = fmaxf(m, l);
    }
#pragma unroll
    for (int o = 16; o; o >>= 1) m = fmaxf(m, __shfl_xor_sync(0xffffffffu, m, o));
    __syncwarp();

    // pass 2: fused sum + weighted gather (unrolled x2 for MLP)
    float acc[V];
#pragma unroll
    for (int t = 0; t < V; t++) acc[t] = 0.f;
    float sum = 0.f;

    const float* h = (ACT == 0) ? g_h1 : g_h2;
    int j = rs;
    for (; j + 2 <= re; j += 2) {
        int s0 = g_csrc[j], s1 = g_csrc[j + 1];
        float e0 = __expf(g_elog[j] - m);
        float e1 = __expf(g_elog[j + 1] - m);
        sum += e0 + e1;
        if (V == 4) {
            float4 v0 = *(const float4*)&h[(size_t)s0 * F + lane * 4];
            float4 v1 = *(const float4*)&h[(size_t)s1 * F + lane * 4];
            acc[0] += e0 * v0.x + e1 * v1.x;
            acc[1] += e0 * v0.y + e1 * v1.y;
            acc[2] += e0 * v0.z + e1 * v1.z;
            acc[3] += e0 * v0.w + e1 * v1.w;
        } else {
            float2 v0 = *(const float2*)&h[(size_t)s0 * F + lane * 2];
            float2 v1 = *(const float2*)&h[(size_t)s1 * F + lane * 2];
            acc[0] += e0 * v0.x + e1 * v1.x;
            acc[1] += e0 * v0.y + e1 * v1.y;
        }
    }
    if (j < re) {
        int s0 = g_csrc[j];
        float e0 = __expf(g_elog[j] - m);
        sum += e0;
        if (V == 4) {
            float4 v0 = *(const float4*)&h[(size_t)s0 * F + lane * 4];
            acc[0] += e0 * v0.x; acc[1] += e0 * v0.y;
            acc[2] += e0 * v0.z; acc[3] += e0 * v0.w;
        } else {
            float2 v0 = *(const float2*)&h[(size_t)s0 * F + lane * 2];
            acc[0] += e0 * v0.x; acc[1] += e0 * v0.y;
        }
    }

    float inv = 1.f / (sum + 1e-16f);
#pragma unroll
    for (int t = 0; t < V; t++) {
        float o = acc[t] * inv + __ldg(&bias[lane * V + t]);
        if (ACT == 0) {
            g_x1[(size_t)w * F + lane * V + t] = fmaxf(o, 0.f);
        } else {
            outp[(size_t)w * F + lane * V + t] = 1.f / (1.f + __expf(-o));
        }
    }
}

// ---------------------------------------------------------------------------
// Launch
// ---------------------------------------------------------------------------
extern "C" void kernel_launch(void* const* d_in, const int* in_sizes, int n_in,
                              void* d_out, int out_size) {
    const int*   ei    = (const int*)d_in[0];
    const float* embed = (const float*)d_in[1];
    const float* W1    = (const float*)d_in[2];
    const float* as1   = (const float*)d_in[3];
    const float* ad1   = (const float*)d_in[4];
    const float* b1    = (const float*)d_in[5];
    const float* W2    = (const float*)d_in[6];
    const float* as2   = (const float*)d_in[7];
    const float* ad2   = (const float*)d_in[8];
    const float* b2    = (const float*)d_in[9];
    float* out = (float*)d_out;

    // CSR build
    k_zero<<<(NN + 255) / 256, 256>>>();
    k_hist<<<(ELN + 255) / 256, 256>>>(ei);
    k_scan1<<<NB, 1024>>>();
    k_scan2<<<1, 32>>>();
    k_scan3<<<NB, 1024>>>();
    k_fill<<<(ELN + 255) / 256, 256>>>(ei);

    int warpBlocks = (NN * 32 + 255) / 256;  // warp-per-node kernels
    int gemmBlocks = (NN + 127) / 128;

    // Layer 1
    k_gemm_tc<CC, HH, false><<<gemmBlocks, 256>>>(embed, W1, as1, ad1);
    k_agg<HH, 0><<<warpBlocks, 256>>>(b1, nullptr);

    // Layer 2
    k_gemm_tc<HH, KK, true><<<gemmBlocks, 256>>>(nullptr, W2, as2, ad2);
    k_agg<KK, 1><<<warpBlocks, 256>>>(b2, out);
}